// round 9
// baseline (speedup 1.0000x reference)
#include <cuda_runtime.h>
#include <cuda_bf16.h>

#define EPSV 1e-5f

// ---------------- device scratch ----------------
__device__ __align__(16) unsigned short g_W1h[36 * 17 * 16 * 24];
__device__ __align__(16) unsigned short g_W1l[36 * 17 * 16 * 24];
__device__ __align__(16) unsigned short g_W2h[153 * 6 * 16 * 24];
__device__ __align__(16) unsigned short g_W2l[153 * 6 * 16 * 24];
__device__ float g_B1[272];
__device__ float g_B2[96];
__device__ float g_W3[16 * 480];
__device__ float g_B3[16];
__device__ float g_W4t[48 * 64];     // transposed: [k=c*3+dk][o]
__device__ float g_B4[64];
__device__ __align__(16) unsigned short g_Ph[16 * 2048 * 64];
__device__ __align__(16) unsigned short g_Pl[16 * 2048 * 64];
__device__ __align__(16) unsigned short g_f1h[16 * 272 * 2048];
__device__ __align__(16) unsigned short g_f1l[16 * 272 * 2048];
__device__ float g_f2[16 * 96 * 2048];    // K-split partial 0 (with bias)
__device__ float g_f2b[16 * 96 * 2048];   // K-split partial 1

__constant__ int c_part_of[17] = {1,2,3,1,1,4,4,5,5,2,2,3,3,0,0,0,0};
__constant__ int c_idx_of[17]  = {0,0,0,1,2,0,1,0,1,1,2,1,2,0,1,2,3};
__constant__ int c_len_of[6]   = {4,3,3,3,2,2};

// ---------------- helpers ----------------
__device__ __forceinline__ void split_bf16(float x, unsigned short& h, unsigned short& l) {
    __nv_bfloat16 bh = __float2bfloat16(x);
    float r = x - __bfloat162float(bh);
    __nv_bfloat16 bl = __float2bfloat16(r);
    h = __bfloat16_as_ushort(bh);
    l = __bfloat16_as_ushort(bl);
}

__device__ __forceinline__ void ldsm4(unsigned r[4], const void* p) {
    unsigned a = (unsigned)__cvta_generic_to_shared(p);
    asm volatile("ldmatrix.sync.aligned.m8n8.x4.shared.b16 {%0,%1,%2,%3},[%4];"
                 : "=r"(r[0]), "=r"(r[1]), "=r"(r[2]), "=r"(r[3]) : "r"(a));
}

__device__ __forceinline__ void mma_bf16(float* c, const unsigned* a, unsigned b0, unsigned b1) {
    asm volatile("mma.sync.aligned.m16n8k16.row.col.f32.bf16.bf16.f32 "
                 "{%0,%1,%2,%3},{%4,%5,%6,%7},{%8,%9},{%0,%1,%2,%3};"
                 : "+f"(c[0]), "+f"(c[1]), "+f"(c[2]), "+f"(c[3])
                 : "r"(a[0]), "r"(a[1]), "r"(a[2]), "r"(a[3]), "r"(b0), "r"(b1));
}

__device__ __forceinline__ void cpa16(void* dst, const void* src) {
    unsigned d = (unsigned)__cvta_generic_to_shared(dst);
    asm volatile("cp.async.cg.shared.global [%0], [%1], 16;" :: "r"(d), "l"(src));
}
__device__ __forceinline__ void cpa16z(void* dst, const void* src, bool valid) {
    unsigned d = (unsigned)__cvta_generic_to_shared(dst);
    int sz = valid ? 16 : 0;
    asm volatile("cp.async.cg.shared.global [%0], [%1], 16, %2;" :: "r"(d), "l"(src), "r"(sz));
}
#define CP_COMMIT() asm volatile("cp.async.commit_group;")
#define CP_WAIT0()  asm volatile("cp.async.wait_group 0;")

// ---------------- single fused prep kernel (656 blocks x 256 thr) ----------------
__global__ void prepAll(const float* __restrict__ poses,
                        const float* __restrict__ A1, const float* __restrict__ w1,
                        const float* __restrict__ b1, const float* __restrict__ g1,
                        const float* __restrict__ be1, const float* __restrict__ m1,
                        const float* __restrict__ v1,
                        const float* __restrict__ A2, const float* __restrict__ w2,
                        const float* __restrict__ b2, const float* __restrict__ g2,
                        const float* __restrict__ be2, const float* __restrict__ m2,
                        const float* __restrict__ v2,
                        const float* __restrict__ w3, const float* __restrict__ b3,
                        const float* __restrict__ g3, const float* __restrict__ be3,
                        const float* __restrict__ m3, const float* __restrict__ v3,
                        const float* __restrict__ w4, const float* __restrict__ b4,
                        const float* __restrict__ g4, const float* __restrict__ be4,
                        const float* __restrict__ m4, const float* __restrict__ v4) {
    const int bid = blockIdx.x;
    if (bid < 256) {
        const int n = bid >> 4, tb = (bid & 15) * 128;
        for (int idx = threadIdx.x; idx < 128 * 64; idx += 256) {
            int tl = idx >> 6, col = idx & 63;
            int t = tb + tl;
            float v = (col < 51) ? poses[((size_t)n * 2048 + t) * 51 + col] : 0.f;
            unsigned short h, l;
            split_bf16(v, h, l);
            size_t o = ((size_t)n * 2048 + t) * 64 + col;
            g_Ph[o] = h; g_Pl[o] = l;
        }
    } else if (bid < 528) {
        int cw = bid - 256;
        int c = cw / 17, w = cw % 17;
        int mt = cw >> 4, row = cw & 15;
        float s = g1[cw] * rsqrtf(v1[cw] + EPSV);
        for (int e = threadIdx.x; e < 36 * 24; e += 256) {
            int it = e / 24, col = e % 24;
            int dt = it >> 2, rc = it & 3;
            int r = rc * 16 + col;
            float val = 0.f;
            if (col < 16 && r < 51) {
                int u = r / 3, ci = r % 3;
                for (int k = 0; k < 5; k++)
                    for (int dv = 0; dv < 5; dv++) {
                        int v = u - dv + 2;
                        if (v >= 0 && v < 17)
                            val += A1[(k * 17 + v) * 17 + w] *
                                   w1[(((k * 16 + c) * 3 + ci) * 9 + dt) * 5 + dv];
                    }
                val *= s;
            }
            unsigned short h, l;
            split_bf16(val, h, l);
            int idx = ((it * 17 + mt) * 16 + row) * 24 + col;
            g_W1h[idx] = h; g_W1l[idx] = l;
        }
        if (threadIdx.x == 0) {
            float bias = 0.f;
            for (int k = 0; k < 5; k++) {
                float sa = 0.f;
                for (int v = 0; v < 17; v++) sa += A1[(k * 17 + v) * 17 + w];
                bias += b1[k * 16 + c] * sa;
            }
            g_B1[cw] = (bias - m1[cw]) * s + be1[cw];
        }
    } else if (bid < 624) {
        int cw = bid - 528;
        int c = cw / 6, w = cw % 6;
        int mt = cw >> 4, row = cw & 15;
        float s = g2[cw] * rsqrtf(v2[cw] + EPSV);
        for (int e = threadIdx.x; e < 153 * 24; e += 256) {
            int it = e / 24, col = e % 24;
            int cc = it / 9, dt = it % 9;
            int ch = cc * 16 + col;
            float val = 0.f;
            if (col < 16) {
                int f = ch / 17, jt = ch % 17;
                int p = c_part_of[jt], j = c_idx_of[jt], ln = c_len_of[p];
                int ci = f * ln + j;
                for (int k = 0; k < 5; k++)
                    for (int v = 0; v < 6; v++) {
                        int dp = p - v + 1;
                        if (dp >= 0 && dp < 3)
                            val += A2[(k * 6 + v) * 6 + w] *
                                   w2[(((k * 16 + c) * 64 + ci) * 9 + dt) * 3 + dp];
                    }
                val *= s;
            }
            unsigned short h, l;
            split_bf16(val, h, l);
            int idx = ((it * 6 + mt) * 16 + row) * 24 + col;
            g_W2h[idx] = h; g_W2l[idx] = l;
        }
        if (threadIdx.x == 0) {
            float bias = 0.f;
            for (int k = 0; k < 5; k++) {
                float sa = 0.f;
                for (int v = 0; v < 6; v++) sa += A2[(k * 6 + v) * 6 + w];
                bias += b2[k * 16 + c] * sa;
            }
            g_B2[cw] = (bias - m2[cw]) * s + be2[cw];
        }
    } else {
        int base = (bid - 624) * 256 + threadIdx.x;
        if (base < 7680) {
            int o = base / 480;
            g_W3[base] = w3[base] * (g3[o] * rsqrtf(v3[o] + EPSV));
        }
        if (base < 3072) {
            int o = base / 48, k = base % 48;
            g_W4t[k * 64 + o] = w4[base] * (g4[o] * rsqrtf(v4[o] + EPSV));
        }
        if (base < 16) {
            float s = g3[base] * rsqrtf(v3[base] + EPSV);
            g_B3[base] = (b3[base] - m3[base]) * s + be3[base];
        }
        if (base >= 32 && base < 96) {
            int o = base - 32;
            float s = g4[o] * rsqrtf(v4[o] + EPSV);
            g_B4[o] = (b4[o] - m4[o]) * s + be4[o];
        }
    }
}

// ---------------- stage 1 tensor GEMM ----------------
#define K1_XOFF 15360
#define K1_XSZ  38016
__global__ void __launch_bounds__(256, 2) k1() {
    extern __shared__ char sm[];
    const int n = blockIdx.y, t0 = blockIdx.x * 256;
    const int z = blockIdx.z;
    const int mt0 = (z == 0) ? 0 : 1 + z * 4;
    const int mcount = (z == 0) ? 5 : 4;
    const int tid = threadIdx.x, lane = tid & 31, w = tid >> 5;

    char* Xh = sm + K1_XOFF;
    char* Xl = sm + K1_XOFF + K1_XSZ;

    auto prefW = [&](int it, char* buf) {
        const char* srcH = (const char*)(g_W1h + (size_t)(it * 17 + mt0) * 384);
        const char* srcL = (const char*)(g_W1l + (size_t)(it * 17 + mt0) * 384);
        int cnt = mcount * 48;
        for (int i = tid; i < cnt; i += 256) {
            cpa16(buf + i * 16, srcH + i * 16);
            cpa16(buf + 3840 + i * 16, srcL + i * 16);
        }
    };

    for (int i = tid; i < 264 * 8; i += 256) {
        int row = i >> 3, q = i & 7;
        int t = t0 - 4 + row;
        bool valid = (t >= 0 && t < 2048);
        size_t so = ((size_t)n * 2048 + (valid ? t : 0)) * 64 + q * 8;
        cpa16z(Xh + row * 144 + q * 16, g_Ph + so, valid);
        cpa16z(Xl + row * 144 + q * 16, g_Pl + so, valid);
    }
    prefW(0, sm);
    CP_COMMIT();

    float C[5][4][4];
#pragma unroll
    for (int i = 0; i < 5; i++)
#pragma unroll
        for (int j = 0; j < 4; j++)
#pragma unroll
            for (int q = 0; q < 4; q++) C[i][j][q] = 0.f;

    const int lrow = (lane & 15) * 48 + (lane >> 4) * 16;

    for (int it = 0; it < 36; it++) {
        char* buf = sm + (it & 1) * 7680;
        CP_WAIT0();
        __syncthreads();
        if (it + 1 < 36) { prefW(it + 1, sm + ((it + 1) & 1) * 7680); CP_COMMIT(); }

        const int dt = it >> 2, rc = it & 3;
        const int colb = (rc * 16 + (lane & 3) * 2) * 2;
        unsigned bh[4][2], bl[4][2];
#pragma unroll
        for (int nb = 0; nb < 4; nb++) {
            int tt = w * 32 + nb * 8 + (lane >> 2) + dt;
            const char* ph = Xh + tt * 144 + colb;
            const char* pl = Xl + tt * 144 + colb;
            bh[nb][0] = *(const unsigned*)ph; bh[nb][1] = *(const unsigned*)(ph + 16);
            bl[nb][0] = *(const unsigned*)pl; bl[nb][1] = *(const unsigned*)(pl + 16);
        }
        for (int mi = 0; mi < mcount; mi++) {
            unsigned Ah[4], Al[4];
            ldsm4(Ah, buf + mi * 768 + lrow);
            ldsm4(Al, buf + 3840 + mi * 768 + lrow);
#pragma unroll
            for (int nb = 0; nb < 4; nb++) {
                mma_bf16(C[mi][nb], Ah, bh[nb][0], bh[nb][1]);
                mma_bf16(C[mi][nb], Ah, bl[nb][0], bl[nb][1]);
                mma_bf16(C[mi][nb], Al, bh[nb][0], bh[nb][1]);
            }
        }
    }

    for (int mi = 0; mi < mcount; mi++) {
#pragma unroll
        for (int nb = 0; nb < 4; nb++) {
            int ch0 = (mt0 + mi) * 16 + (lane >> 2);
            int tt = t0 + w * 32 + nb * 8 + (lane & 3) * 2;
            float b0 = g_B1[ch0], b1 = g_B1[ch0 + 8];
            unsigned short h0, l0, h1, l1;
            size_t o0 = ((size_t)n * 272 + ch0) * 2048 + tt;
            split_bf16(C[mi][nb][0] + b0, h0, l0);
            split_bf16(C[mi][nb][1] + b0, h1, l1);
            *(unsigned*)&g_f1h[o0] = (unsigned)h0 | ((unsigned)h1 << 16);
            *(unsigned*)&g_f1l[o0] = (unsigned)l0 | ((unsigned)l1 << 16);
            size_t o1 = ((size_t)n * 272 + ch0 + 8) * 2048 + tt;
            split_bf16(C[mi][nb][2] + b1, h0, l0);
            split_bf16(C[mi][nb][3] + b1, h1, l1);
            *(unsigned*)&g_f1h[o1] = (unsigned)h0 | ((unsigned)h1 << 16);
            *(unsigned*)&g_f1l[o1] = (unsigned)l0 | ((unsigned)l1 << 16);
        }
    }
}

// ---------------- stage 2 tensor GEMM (K-split over z) ----------------
#define K2_WSZ 18432
#define K2_XB  25344
__global__ void __launch_bounds__(256, 2) k2() {
    extern __shared__ char sm[];
    const int n = blockIdx.y, t0 = blockIdx.x * 256;
    const int zz = blockIdx.z;
    const int cc0 = zz ? 9 : 0;
    const int ncc = zz ? 8 : 9;
    const int tid = threadIdx.x, lane = tid & 31, w = tid >> 5;
    const int g = tid & 15, jj = tid >> 4;

    unsigned sh[9], sl[9];

    auto prefW = [&](int it, char* buf) {
        const char* srcH = (const char*)(g_W2h + (size_t)it * 2304);
        const char* srcL = (const char*)(g_W2l + (size_t)it * 2304);
        for (int i = tid; i < 288; i += 256) {
            cpa16(buf + i * 16, srcH + i * 16);
            cpa16(buf + 4608 + i * 16, srcL + i * 16);
        }
    };
    auto loadX = [&](int cc) {
        size_t base = ((size_t)n * 272 + cc * 16 + g) * 2048;
#pragma unroll
        for (int i = 0; i < 9; i++) {
            int p = jj + 16 * i;
            sh[i] = 0; sl[i] = 0;
            if (p < 132) {
                int t = t0 - 4 + 2 * p;
                if (t >= 0 && t < 2048) {
                    sh[i] = *(const unsigned*)(g_f1h + base + t);
                    sl[i] = *(const unsigned*)(g_f1l + base + t);
                }
            }
        }
    };
    auto stsX = [&](int buf) {
        unsigned short* Xh = (unsigned short*)(sm + K2_WSZ + buf * K2_XB);
        unsigned short* Xl = (unsigned short*)(sm + K2_WSZ + buf * K2_XB + 12672);
#pragma unroll
        for (int i = 0; i < 9; i++) {
            int p = jj + 16 * i;
            if (p < 132) {
                Xh[(2 * p) * 24 + g] = (unsigned short)(sh[i] & 0xffff);
                Xh[(2 * p + 1) * 24 + g] = (unsigned short)(sh[i] >> 16);
                Xl[(2 * p) * 24 + g] = (unsigned short)(sl[i] & 0xffff);
                Xl[(2 * p + 1) * 24 + g] = (unsigned short)(sl[i] >> 16);
            }
        }
    };

    loadX(cc0);
    stsX(0);
    prefW(cc0 * 9, sm);
    CP_COMMIT();

    float C[6][4][4];
#pragma unroll
    for (int i = 0; i < 6; i++)
#pragma unroll
        for (int j = 0; j < 4; j++)
#pragma unroll
            for (int q = 0; q < 4; q++) C[i][j][q] = 0.f;

    const int lrow = (lane & 15) * 48 + (lane >> 4) * 16;
    const int colb = ((lane & 3) * 2) * 2;
    const int nit = ncc * 9;

    for (int i = 0; i < nit; i++) {
        const int ccl = i / 9, dt = i - ccl * 9;
        char* buf = sm + (i & 1) * 9216;
        CP_WAIT0();
        __syncthreads();
        if (i + 1 < nit) { prefW(cc0 * 9 + i + 1, sm + ((i + 1) & 1) * 9216); CP_COMMIT(); }
        if (dt == 0 && ccl + 1 < ncc) loadX(cc0 + ccl + 1);
        if (dt == 7 && ccl + 1 < ncc) stsX((ccl + 1) & 1);

        const char* Xh = sm + K2_WSZ + (ccl & 1) * K2_XB;
        const char* Xl = Xh + 12672;
        unsigned bh[4][2], bl[4][2];
#pragma unroll
        for (int nb = 0; nb < 4; nb++) {
            int tt = w * 32 + nb * 8 + (lane >> 2) + dt;
            const char* ph = Xh + tt * 48 + colb;
            const char* pl = Xl + tt * 48 + colb;
            bh[nb][0] = *(const unsigned*)ph; bh[nb][1] = *(const unsigned*)(ph + 16);
            bl[nb][0] = *(const unsigned*)pl; bl[nb][1] = *(const unsigned*)(pl + 16);
        }
#pragma unroll
        for (int mi = 0; mi < 6; mi++) {
            unsigned Ah[4], Al[4];
            ldsm4(Ah, buf + mi * 768 + lrow);
            ldsm4(Al, buf + 4608 + mi * 768 + lrow);
#pragma unroll
            for (int nb = 0; nb < 4; nb++) {
                mma_bf16(C[mi][nb], Ah, bh[nb][0], bh[nb][1]);
                mma_bf16(C[mi][nb], Ah, bl[nb][0], bl[nb][1]);
                mma_bf16(C[mi][nb], Al, bh[nb][0], bh[nb][1]);
            }
        }
    }

    float* dst = zz ? g_f2b : g_f2;
#pragma unroll
    for (int mi = 0; mi < 6; mi++) {
#pragma unroll
        for (int nb = 0; nb < 4; nb++) {
            int ch0 = mi * 16 + (lane >> 2);
            int tt = t0 + w * 32 + nb * 8 + (lane & 3) * 2;
            float b0 = zz ? 0.f : g_B2[ch0];
            float b1 = zz ? 0.f : g_B2[ch0 + 8];
            float2 v0 = make_float2(C[mi][nb][0] + b0, C[mi][nb][1] + b0);
            float2 v1 = make_float2(C[mi][nb][2] + b1, C[mi][nb][3] + b1);
            *(float2*)&dst[((size_t)n * 96 + ch0) * 2048 + tt] = v0;
            *(float2*)&dst[((size_t)n * 96 + ch0 + 8) * 2048 + tt] = v1;
        }
    }
}

// ---------------- stages 3+4 fused (bank-conflict-free, 2 CTAs/SM) ----------------
// smem: F2s [96][144] | F3s [16][132] | W3s [16][481]  = 94528 B
__global__ void __launch_bounds__(256, 2) k34(float* __restrict__ out) {
    extern __shared__ float smf[];
    float* F2s = smf;
    float* F3s = smf + 96 * 144;
    float* W3s = F3s + 16 * 132;
    const int n = blockIdx.y;
    const int t0 = blockIdx.x * 128;
    const int tid = threadIdx.x;

    for (int idx = tid; idx < 96 * 144; idx += 256) {
        int c = idx / 144, q = idx - c * 144;
        int t = t0 - 3 + q;
        float v = 0.f;
        if (q < 136 && t >= 0 && t < 2048) {
            size_t o = ((size_t)n * 96 + c) * 2048 + t;
            v = g_f2[o] + g_f2b[o];
        }
        F2s[idx] = v;
    }
    for (int idx = tid; idx < 16 * 480; idx += 256) {
        int o = idx / 480, k = idx - o * 480;
        W3s[o * 481 + k] = g_W3[idx];
    }
    __syncthreads();

    // f3: idx = q*16 + o (q 0..16, o 0..15) -> activations broadcast across lanes,
    //     weights stride 481 (== 1 mod 32) -> conflict-free banks
    for (int idx = tid; idx < 272; idx += 256) {
        int q = idx >> 4, o = idx & 15;
        int tp0 = q * 8;
        float bb = __ldg(&g_B3[o]);
        float acc[8];
#pragma unroll
        for (int j = 0; j < 8; j++) acc[j] = bb;
        const float* wr = W3s + o * 481;
        for (int c = 0; c < 96; c++) {
            const float* fp = F2s + c * 144 + tp0;
            float4 A = *(const float4*)fp;
            float4 Bv = *(const float4*)(fp + 4);
            float4 Cv = *(const float4*)(fp + 8);
            float f[12] = {A.x, A.y, A.z, A.w, Bv.x, Bv.y, Bv.z, Bv.w,
                           Cv.x, Cv.y, Cv.z, Cv.w};
            const float* wc = wr + c * 5;
#pragma unroll
            for (int dk = 0; dk < 5; dk++) {
                float wv = wc[dk];
#pragma unroll
                for (int j = 0; j < 8; j++) acc[j] = fmaf(wv, f[j + dk], acc[j]);
            }
        }
#pragma unroll
        for (int j = 0; j < 8; j++) {
            int tp = tp0 + j;
            int t3 = t0 - 1 + tp;
            float v = 0.f;
            if (tp < 130 && t3 >= 0 && t3 < 2048)
                v = acc[j] > 0.f ? acc[j] : 0.01f * acc[j];
            if (tp < 132) F3s[o * 132 + tp] = v;
        }
    }
    __syncthreads();

    // f4: weights via uniform __ldg float4 (L1 broadcast), coalesced STG.128
#pragma unroll
    for (int u = 0; u < 8; u++) {
        int idx = tid + u * 256;
        int tl = idx & 127, o0 = (idx >> 7) * 4;
        float acc[4];
#pragma unroll
        for (int i = 0; i < 4; i++) acc[i] = __ldg(&g_B4[o0 + i]);
        for (int c = 0; c < 16; c++) {
            float fv[3] = {F3s[c * 132 + tl], F3s[c * 132 + tl + 1], F3s[c * 132 + tl + 2]};
#pragma unroll
            for (int dk = 0; dk < 3; dk++) {
                float4 wv = __ldg((const float4*)(g_W4t + (c * 3 + dk) * 64 + o0));
                acc[0] = fmaf(wv.x, fv[dk], acc[0]);
                acc[1] = fmaf(wv.y, fv[dk], acc[1]);
                acc[2] = fmaf(wv.z, fv[dk], acc[2]);
                acc[3] = fmaf(wv.w, fv[dk], acc[3]);
            }
        }
        float4 r;
        r.x = acc[0] > 0.f ? acc[0] : 0.01f * acc[0];
        r.y = acc[1] > 0.f ? acc[1] : 0.01f * acc[1];
        r.z = acc[2] > 0.f ? acc[2] : 0.01f * acc[2];
        r.w = acc[3] > 0.f ? acc[3] : 0.01f * acc[3];
        *(float4*)&out[((size_t)n * 2048 + t0 + tl) * 64 + o0] = r;
    }
}

// ---------------- launch ----------------
extern "C" void kernel_launch(void* const* d_in, const int* in_sizes, int n_in,
                              void* d_out, int out_size) {
    (void)in_sizes; (void)n_in; (void)out_size;
    const float* poses = (const float*)d_in[0];
    const float* A1 = (const float*)d_in[1];
    const float* A2 = (const float*)d_in[2];
    const float* w1 = (const float*)d_in[3];
    const float* b1 = (const float*)d_in[4];
    const float* g1 = (const float*)d_in[5];
    const float* be1 = (const float*)d_in[6];
    const float* m1 = (const float*)d_in[7];
    const float* v1 = (const float*)d_in[8];
    const float* w2 = (const float*)d_in[9];
    const float* b2 = (const float*)d_in[10];
    const float* g2 = (const float*)d_in[11];
    const float* be2 = (const float*)d_in[12];
    const float* m2 = (const float*)d_in[13];
    const float* v2 = (const float*)d_in[14];
    const float* w3 = (const float*)d_in[15];
    const float* b3 = (const float*)d_in[16];
    const float* g3 = (const float*)d_in[17];
    const float* be3 = (const float*)d_in[18];
    const float* m3 = (const float*)d_in[19];
    const float* v3 = (const float*)d_in[20];
    const float* w4 = (const float*)d_in[21];
    const float* b4 = (const float*)d_in[22];
    const float* g4 = (const float*)d_in[23];
    const float* be4 = (const float*)d_in[24];
    const float* m4 = (const float*)d_in[25];
    const float* v4 = (const float*)d_in[26];
    float* out = (float*)d_out;

    size_t sm1 = 91392;
    size_t sm2 = 69120;
    size_t sm34 = (96 * 144 + 16 * 132 + 16 * 481) * sizeof(float);  // 94528
    cudaFuncSetAttribute(k1, cudaFuncAttributeMaxDynamicSharedMemorySize, (int)sm1);
    cudaFuncSetAttribute(k2, cudaFuncAttributeMaxDynamicSharedMemorySize, (int)sm2);
    cudaFuncSetAttribute(k34, cudaFuncAttributeMaxDynamicSharedMemorySize, (int)sm34);

    prepAll<<<656, 256>>>(poses,
                          A1, w1, b1, g1, be1, m1, v1,
                          A2, w2, b2, g2, be2, m2, v2,
                          w3, b3, g3, be3, m3, v3,
                          w4, b4, g4, be4, m4, v4);
    k1<<<dim3(8, 16, 4), 256, sm1>>>();
    k2<<<dim3(8, 16, 2), 256, sm2>>>();
    k34<<<dim3(16, 16), 256, sm34>>>(out);
}

// round 11
// speedup vs baseline: 1.2330x; 1.2330x over previous
#include <cuda_runtime.h>
#include <cuda_fp16.h>

#define EPSV 1e-5f

// ---------------- device scratch ----------------
__device__ __align__(16) unsigned short g_W1h[36 * 17 * 16 * 24];   // fp16 bits
__device__ __align__(16) unsigned short g_W2h[153 * 6 * 16 * 24];   // fp16 bits
__device__ float g_B1[272];
__device__ float g_B2[96];
__device__ float g_W3[16 * 480];
__device__ float g_B3[16];
__device__ float g_W4t[48 * 64];     // transposed: [k=c*3+dk][o]
__device__ float g_B4[64];
__device__ __align__(16) unsigned short g_Ph[16 * 2048 * 64];       // poses fp16 hi
__device__ __align__(16) unsigned short g_Pl[16 * 2048 * 64];       // poses fp16 lo
__device__ __align__(16) unsigned short g_f1h[16 * 272 * 2048];
__device__ __align__(16) unsigned short g_f1l[16 * 272 * 2048];
__device__ float g_f2[16 * 96 * 2048];    // K-split partial 0 (with bias)
__device__ float g_f2b[16 * 96 * 2048];   // K-split partial 1

__constant__ int c_part_of[17] = {1,2,3,1,1,4,4,5,5,2,2,3,3,0,0,0,0};
__constant__ int c_idx_of[17]  = {0,0,0,1,2,0,1,0,1,1,2,1,2,0,1,2,3};
__constant__ int c_len_of[6]   = {4,3,3,3,2,2};

// ---------------- helpers ----------------
__device__ __forceinline__ void split_fp16(float x, unsigned short& h, unsigned short& l) {
    __half hh = __float2half_rn(x);
    float r = x - __half2float(hh);
    __half ll = __float2half_rn(r);
    h = __half_as_ushort(hh); l = __half_as_ushort(ll);
}
__device__ __forceinline__ void ldsm4(unsigned r[4], const void* p) {
    unsigned a = (unsigned)__cvta_generic_to_shared(p);
    asm volatile("ldmatrix.sync.aligned.m8n8.x4.shared.b16 {%0,%1,%2,%3},[%4];"
                 : "=r"(r[0]), "=r"(r[1]), "=r"(r[2]), "=r"(r[3]) : "r"(a));
}
__device__ __forceinline__ void mma_fp16(float* c, const unsigned* a, unsigned b0, unsigned b1) {
    asm volatile("mma.sync.aligned.m16n8k16.row.col.f32.f16.f16.f32 "
                 "{%0,%1,%2,%3},{%4,%5,%6,%7},{%8,%9},{%0,%1,%2,%3};"
                 : "+f"(c[0]), "+f"(c[1]), "+f"(c[2]), "+f"(c[3])
                 : "r"(a[0]), "r"(a[1]), "r"(a[2]), "r"(a[3]), "r"(b0), "r"(b1));
}
__device__ __forceinline__ void cpa16(void* dst, const void* src) {
    unsigned d = (unsigned)__cvta_generic_to_shared(dst);
    asm volatile("cp.async.cg.shared.global [%0], [%1], 16;" :: "r"(d), "l"(src));
}
__device__ __forceinline__ void cpa16z(void* dst, const void* src, bool valid) {
    unsigned d = (unsigned)__cvta_generic_to_shared(dst);
    int sz = valid ? 16 : 0;
    asm volatile("cp.async.cg.shared.global [%0], [%1], 16, %2;" :: "r"(d), "l"(src), "r"(sz));
}
#define CP_COMMIT() asm volatile("cp.async.commit_group;")
#define CP_WAIT0()  asm volatile("cp.async.wait_group 0;")

// ---------------- fused prep (656 blocks x 256 thr) ----------------
__global__ void prepAll(const float* __restrict__ poses,
                        const float* __restrict__ A1, const float* __restrict__ w1,
                        const float* __restrict__ b1, const float* __restrict__ g1,
                        const float* __restrict__ be1, const float* __restrict__ m1,
                        const float* __restrict__ v1,
                        const float* __restrict__ A2, const float* __restrict__ w2,
                        const float* __restrict__ b2, const float* __restrict__ g2,
                        const float* __restrict__ be2, const float* __restrict__ m2,
                        const float* __restrict__ v2,
                        const float* __restrict__ w3, const float* __restrict__ b3,
                        const float* __restrict__ g3, const float* __restrict__ be3,
                        const float* __restrict__ m3, const float* __restrict__ v3,
                        const float* __restrict__ w4, const float* __restrict__ b4,
                        const float* __restrict__ g4, const float* __restrict__ be4,
                        const float* __restrict__ m4, const float* __restrict__ v4) {
    const int bid = blockIdx.x;
    if (bid < 256) {
        const int n = bid >> 4, tb = (bid & 15) * 128;
        for (int idx = threadIdx.x; idx < 128 * 64; idx += 256) {
            int tl = idx >> 6, col = idx & 63;
            int t = tb + tl;
            float v = (col < 51) ? poses[((size_t)n * 2048 + t) * 51 + col] : 0.f;
            unsigned short h, l; split_fp16(v, h, l);
            size_t o = ((size_t)n * 2048 + t) * 64 + col;
            g_Ph[o] = h; g_Pl[o] = l;
        }
    } else if (bid < 528) {
        int cw = bid - 256;
        int c = cw / 17, w = cw % 17;
        int mt = cw >> 4, row = cw & 15;
        float s = g1[cw] * rsqrtf(v1[cw] + EPSV);
        for (int e = threadIdx.x; e < 36 * 24; e += 256) {
            int it = e / 24, col = e % 24;
            int dt = it >> 2, rc = it & 3;
            int r = rc * 16 + col;
            float val = 0.f;
            if (col < 16 && r < 51) {
                int u = r / 3, ci = r % 3;
                for (int k = 0; k < 5; k++)
                    for (int dv = 0; dv < 5; dv++) {
                        int v = u - dv + 2;
                        if (v >= 0 && v < 17)
                            val += A1[(k * 17 + v) * 17 + w] *
                                   w1[(((k * 16 + c) * 3 + ci) * 9 + dt) * 5 + dv];
                    }
                val *= s;
            }
            g_W1h[((it * 17 + mt) * 16 + row) * 24 + col] =
                __half_as_ushort(__float2half_rn(val));
        }
        if (threadIdx.x == 0) {
            float bias = 0.f;
            for (int k = 0; k < 5; k++) {
                float sa = 0.f;
                for (int v = 0; v < 17; v++) sa += A1[(k * 17 + v) * 17 + w];
                bias += b1[k * 16 + c] * sa;
            }
            g_B1[cw] = (bias - m1[cw]) * s + be1[cw];
        }
    } else if (bid < 624) {
        int cw = bid - 528;
        int c = cw / 6, w = cw % 6;
        int mt = cw >> 4, row = cw & 15;
        float s = g2[cw] * rsqrtf(v2[cw] + EPSV);
        for (int e = threadIdx.x; e < 153 * 24; e += 256) {
            int it = e / 24, col = e % 24;
            int cc = it / 9, dt = it % 9;
            int ch = cc * 16 + col;
            float val = 0.f;
            if (col < 16) {
                int f = ch / 17, jt = ch % 17;
                int p = c_part_of[jt], j = c_idx_of[jt], ln = c_len_of[p];
                int ci = f * ln + j;
                for (int k = 0; k < 5; k++)
                    for (int v = 0; v < 6; v++) {
                        int dp = p - v + 1;
                        if (dp >= 0 && dp < 3)
                            val += A2[(k * 6 + v) * 6 + w] *
                                   w2[(((k * 16 + c) * 64 + ci) * 9 + dt) * 3 + dp];
                    }
                val *= s;
            }
            g_W2h[((it * 6 + mt) * 16 + row) * 24 + col] =
                __half_as_ushort(__float2half_rn(val));
        }
        if (threadIdx.x == 0) {
            float bias = 0.f;
            for (int k = 0; k < 5; k++) {
                float sa = 0.f;
                for (int v = 0; v < 6; v++) sa += A2[(k * 6 + v) * 6 + w];
                bias += b2[k * 16 + c] * sa;
            }
            g_B2[cw] = (bias - m2[cw]) * s + be2[cw];
        }
    } else {
        int base = (bid - 624) * 256 + threadIdx.x;
        if (base < 7680) {
            int o = base / 480;
            g_W3[base] = w3[base] * (g3[o] * rsqrtf(v3[o] + EPSV));
        }
        if (base < 3072) {
            int o = base / 48, k = base % 48;
            g_W4t[k * 64 + o] = w4[base] * (g4[o] * rsqrtf(v4[o] + EPSV));
        }
        if (base < 16) {
            float s = g3[base] * rsqrtf(v3[base] + EPSV);
            g_B3[base] = (b3[base] - m3[base]) * s + be3[base];
        }
        if (base >= 32 && base < 96) {
            int o = base - 32;
            float s = g4[o] * rsqrtf(v4[o] + EPSV);
            g_B4[o] = (b4[o] - m4[o]) * s + be4[o];
        }
    }
}

// ---------------- stage 1 tensor GEMM (fp16 2-term) ----------------
// smem: Wbuf0 3840 | Wbuf1 3840 | Xh 38016 | Xl 38016 = 83712
#define K1_XOFF 7680
#define K1_XSZ  38016
__global__ void __launch_bounds__(256, 2) k1() {
    extern __shared__ char sm[];
    const int n = blockIdx.y, t0 = blockIdx.x * 256;
    const int z = blockIdx.z;
    const int mt0 = (z == 0) ? 0 : 1 + z * 4;
    const int mcount = (z == 0) ? 5 : 4;
    const int tid = threadIdx.x, lane = tid & 31, w = tid >> 5;
    char* Xh = sm + K1_XOFF;
    char* Xl = sm + K1_XOFF + K1_XSZ;

    auto prefW = [&](int it, char* buf) {
        const char* srcH = (const char*)(g_W1h + (size_t)(it * 17 + mt0) * 384);
        int cnt = mcount * 48;
        for (int i = tid; i < cnt; i += 256) cpa16(buf + i * 16, srcH + i * 16);
    };
    for (int i = tid; i < 264 * 8; i += 256) {
        int row = i >> 3, q = i & 7;
        int t = t0 - 4 + row;
        bool valid = (t >= 0 && t < 2048);
        size_t so = ((size_t)n * 2048 + (valid ? t : 0)) * 64 + q * 8;
        cpa16z(Xh + row * 144 + q * 16, g_Ph + so, valid);
        cpa16z(Xl + row * 144 + q * 16, g_Pl + so, valid);
    }
    prefW(0, sm); CP_COMMIT();

    float C[5][4][4];
#pragma unroll
    for (int i = 0; i < 5; i++)
#pragma unroll
        for (int j = 0; j < 4; j++)
#pragma unroll
            for (int q = 0; q < 4; q++) C[i][j][q] = 0.f;
    const int lrow = (lane & 15) * 48 + (lane >> 4) * 16;

    for (int it = 0; it < 36; it++) {
        char* buf = sm + (it & 1) * 3840;
        CP_WAIT0();
        __syncthreads();
        if (it + 1 < 36) { prefW(it + 1, sm + ((it + 1) & 1) * 3840); CP_COMMIT(); }
        const int dt = it >> 2, rc = it & 3;
        const int colb = (rc * 16 + (lane & 3) * 2) * 2;
        unsigned bh[4][2], bl[4][2];
#pragma unroll
        for (int nb = 0; nb < 4; nb++) {
            int tt = w * 32 + nb * 8 + (lane >> 2) + dt;
            const char* ph = Xh + tt * 144 + colb;
            const char* pl = Xl + tt * 144 + colb;
            bh[nb][0] = *(const unsigned*)ph; bh[nb][1] = *(const unsigned*)(ph + 16);
            bl[nb][0] = *(const unsigned*)pl; bl[nb][1] = *(const unsigned*)(pl + 16);
        }
        for (int mi = 0; mi < mcount; mi++) {
            unsigned Ah[4];
            ldsm4(Ah, buf + mi * 768 + lrow);
#pragma unroll
            for (int nb = 0; nb < 4; nb++) {
                mma_fp16(C[mi][nb], Ah, bh[nb][0], bh[nb][1]);
                mma_fp16(C[mi][nb], Ah, bl[nb][0], bl[nb][1]);
            }
        }
    }
    for (int mi = 0; mi < mcount; mi++) {
#pragma unroll
        for (int nb = 0; nb < 4; nb++) {
            int ch0 = (mt0 + mi) * 16 + (lane >> 2);
            int tt = t0 + w * 32 + nb * 8 + (lane & 3) * 2;
            float b0 = g_B1[ch0], b1 = g_B1[ch0 + 8];
            unsigned short h0, l0, h1, l1;
            size_t o0 = ((size_t)n * 272 + ch0) * 2048 + tt;
            split_fp16(C[mi][nb][0] + b0, h0, l0);
            split_fp16(C[mi][nb][1] + b0, h1, l1);
            *(unsigned*)&g_f1h[o0] = (unsigned)h0 | ((unsigned)h1 << 16);
            *(unsigned*)&g_f1l[o0] = (unsigned)l0 | ((unsigned)l1 << 16);
            size_t o1 = ((size_t)n * 272 + ch0 + 8) * 2048 + tt;
            split_fp16(C[mi][nb][2] + b1, h0, l0);
            split_fp16(C[mi][nb][3] + b1, h1, l1);
            *(unsigned*)&g_f1h[o1] = (unsigned)h0 | ((unsigned)h1 << 16);
            *(unsigned*)&g_f1l[o1] = (unsigned)l0 | ((unsigned)l1 << 16);
        }
    }
}

// ---------------- stage 2 tensor GEMM (fp16 2-term, K-split over z) ----------------
// smem: Wbuf0 4608 | Wbuf1 4608 | X 2x25344 = 59904
#define K2_WSZ 9216
#define K2_XB  25344
__global__ void __launch_bounds__(256, 2) k2() {
    extern __shared__ char sm[];
    const int n = blockIdx.y, t0 = blockIdx.x * 256;
    const int zz = blockIdx.z;
    const int cc0 = zz ? 9 : 0;
    const int ncc = zz ? 8 : 9;
    const int tid = threadIdx.x, lane = tid & 31, w = tid >> 5;
    const int g = tid & 15, jj = tid >> 4;
    unsigned sh[9], sl[9];

    auto prefW = [&](int it, char* buf) {
        const char* srcH = (const char*)(g_W2h + (size_t)it * 2304);
        for (int i = tid; i < 288; i += 256) cpa16(buf + i * 16, srcH + i * 16);
    };
    auto loadX = [&](int cc) {
        size_t base = ((size_t)n * 272 + cc * 16 + g) * 2048;
#pragma unroll
        for (int i = 0; i < 9; i++) {
            int p = jj + 16 * i;
            sh[i] = 0; sl[i] = 0;
            if (p < 132) {
                int t = t0 - 4 + 2 * p;
                if (t >= 0 && t < 2048) {
                    sh[i] = *(const unsigned*)(g_f1h + base + t);
                    sl[i] = *(const unsigned*)(g_f1l + base + t);
                }
            }
        }
    };
    auto stsX = [&](int buf) {
        unsigned short* Xh = (unsigned short*)(sm + K2_WSZ + buf * K2_XB);
        unsigned short* Xl = (unsigned short*)(sm + K2_WSZ + buf * K2_XB + 12672);
#pragma unroll
        for (int i = 0; i < 9; i++) {
            int p = jj + 16 * i;
            if (p < 132) {
                Xh[(2 * p) * 24 + g] = (unsigned short)(sh[i] & 0xffff);
                Xh[(2 * p + 1) * 24 + g] = (unsigned short)(sh[i] >> 16);
                Xl[(2 * p) * 24 + g] = (unsigned short)(sl[i] & 0xffff);
                Xl[(2 * p + 1) * 24 + g] = (unsigned short)(sl[i] >> 16);
            }
        }
    };

    loadX(cc0);
    stsX(0);
    prefW(cc0 * 9, sm);
    CP_COMMIT();

    float C[6][4][4];
#pragma unroll
    for (int i = 0; i < 6; i++)
#pragma unroll
        for (int j = 0; j < 4; j++)
#pragma unroll
            for (int q = 0; q < 4; q++) C[i][j][q] = 0.f;

    const int lrow = (lane & 15) * 48 + (lane >> 4) * 16;
    const int colb = ((lane & 3) * 2) * 2;
    const int nit = ncc * 9;

    for (int i = 0; i < nit; i++) {
        const int ccl = i / 9, dt = i - ccl * 9;
        char* buf = sm + (i & 1) * 4608;
        CP_WAIT0();
        __syncthreads();
        if (i + 1 < nit) { prefW(cc0 * 9 + i + 1, sm + ((i + 1) & 1) * 4608); CP_COMMIT(); }
        if (dt == 0 && ccl + 1 < ncc) loadX(cc0 + ccl + 1);
        if (dt == 7 && ccl + 1 < ncc) stsX((ccl + 1) & 1);

        const char* Xh = sm + K2_WSZ + (ccl & 1) * K2_XB;
        const char* Xl = Xh + 12672;
        unsigned bh[4][2], bl[4][2];
#pragma unroll
        for (int nb = 0; nb < 4; nb++) {
            int tt = w * 32 + nb * 8 + (lane >> 2) + dt;
            const char* ph = Xh + tt * 48 + colb;
            const char* pl = Xl + tt * 48 + colb;
            bh[nb][0] = *(const unsigned*)ph; bh[nb][1] = *(const unsigned*)(ph + 16);
            bl[nb][0] = *(const unsigned*)pl; bl[nb][1] = *(const unsigned*)(pl + 16);
        }
#pragma unroll
        for (int mi = 0; mi < 6; mi++) {
            unsigned Ah[4];
            ldsm4(Ah, buf + mi * 768 + lrow);
#pragma unroll
            for (int nb = 0; nb < 4; nb++) {
                mma_fp16(C[mi][nb], Ah, bh[nb][0], bh[nb][1]);
                mma_fp16(C[mi][nb], Ah, bl[nb][0], bl[nb][1]);
            }
        }
    }

    float* dst = zz ? g_f2b : g_f2;
#pragma unroll
    for (int mi = 0; mi < 6; mi++) {
#pragma unroll
        for (int nb = 0; nb < 4; nb++) {
            int ch0 = mi * 16 + (lane >> 2);
            int tt = t0 + w * 32 + nb * 8 + (lane & 3) * 2;
            float b0 = zz ? 0.f : g_B2[ch0];
            float b1 = zz ? 0.f : g_B2[ch0 + 8];
            float2 v0 = make_float2(C[mi][nb][0] + b0, C[mi][nb][1] + b0);
            float2 v1 = make_float2(C[mi][nb][2] + b1, C[mi][nb][3] + b1);
            *(float2*)&dst[((size_t)n * 96 + ch0) * 2048 + tt] = v0;
            *(float2*)&dst[((size_t)n * 96 + ch0 + 8) * 2048 + tt] = v1;
        }
    }
}

// ---------------- stages 3+4 fused (balanced f3) ----------------
__global__ void __launch_bounds__(256, 2) k34(float* __restrict__ out) {
    extern __shared__ float smf[];
    float* F2s = smf;
    float* F3s = smf + 96 * 144;
    float* W3s = F3s + 16 * 132;
    const int n = blockIdx.y;
    const int t0 = blockIdx.x * 128;
    const int tid = threadIdx.x;

    for (int idx = tid; idx < 96 * 144; idx += 256) {
        int c = idx / 144, q = idx - c * 144;
        int t = t0 - 3 + q;
        float v = 0.f;
        if (q < 136 && t >= 0 && t < 2048) {
            size_t o = ((size_t)n * 96 + c) * 2048 + t;
            v = g_f2[o] + g_f2b[o];
        }
        F2s[idx] = v;
    }
    for (int idx = tid; idx < 16 * 480; idx += 256) {
        int o = idx / 480, k = idx - o * 480;
        W3s[o * 481 + k] = g_W3[idx];
    }
    __syncthreads();

    {   // main: 256 units (16 q x 16 o), tp = 8q..8q+7 covers tp 0..127
        int q = tid >> 4, o = tid & 15;
        int tp0 = q * 8;
        float bb = __ldg(&g_B3[o]);
        float acc[8];
#pragma unroll
        for (int j = 0; j < 8; j++) acc[j] = bb;
        const float* wr = W3s + o * 481;
        for (int c = 0; c < 96; c++) {
            const float* fp = F2s + c * 144 + tp0;
            float4 A = *(const float4*)fp;
            float4 Bv = *(const float4*)(fp + 4);
            float4 Cv = *(const float4*)(fp + 8);
            float f[12] = {A.x, A.y, A.z, A.w, Bv.x, Bv.y, Bv.z, Bv.w, Cv.x, Cv.y, Cv.z, Cv.w};
            const float* wc = wr + c * 5;
#pragma unroll
            for (int dk = 0; dk < 5; dk++) {
                float wv = wc[dk];
#pragma unroll
                for (int j = 0; j < 8; j++) acc[j] = fmaf(wv, f[j + dk], acc[j]);
            }
        }
#pragma unroll
        for (int j = 0; j < 8; j++) {
            int tp = tp0 + j;
            int t3 = t0 - 1 + tp;
            float v = 0.f;
            if (t3 >= 0 && t3 < 2048)
                v = acc[j] > 0.f ? acc[j] : 0.01f * acc[j];
            F3s[o * 132 + tp] = v;
        }
    }
    if (tid < 16) {   // tail: tp 128..129
        int o = tid;
        float bb = __ldg(&g_B3[o]);
        float a0 = bb, a1 = bb;
        const float* wr = W3s + o * 481;
        for (int c = 0; c < 96; c++) {
            const float* fp = F2s + c * 144 + 128;
            const float* wc = wr + c * 5;
#pragma unroll
            for (int dk = 0; dk < 5; dk++) {
                a0 = fmaf(wc[dk], fp[dk], a0);
                a1 = fmaf(wc[dk], fp[dk + 1], a1);
            }
        }
        int t3 = t0 + 127;
        F3s[o * 132 + 128] = (t3 < 2048) ? (a0 > 0.f ? a0 : 0.01f * a0) : 0.f;
        F3s[o * 132 + 129] = (t3 + 1 < 2048) ? (a1 > 0.f ? a1 : 0.01f * a1) : 0.f;
    }
    __syncthreads();

#pragma unroll
    for (int u = 0; u < 8; u++) {
        int idx = tid + u * 256;
        int tl = idx & 127, o0 = (idx >> 7) * 4;
        float acc[4];
#pragma unroll
        for (int i = 0; i < 4; i++) acc[i] = __ldg(&g_B4[o0 + i]);
        for (int c = 0; c < 16; c++) {
            float fv[3] = {F3s[c * 132 + tl], F3s[c * 132 + tl + 1], F3s[c * 132 + tl + 2]};
#pragma unroll
            for (int dk = 0; dk < 3; dk++) {
                float4 wv = __ldg((const float4*)(g_W4t + (c * 3 + dk) * 64 + o0));
                acc[0] = fmaf(wv.x, fv[dk], acc[0]);
                acc[1] = fmaf(wv.y, fv[dk], acc[1]);
                acc[2] = fmaf(wv.z, fv[dk], acc[2]);
                acc[3] = fmaf(wv.w, fv[dk], acc[3]);
            }
        }
        float4 r;
        r.x = acc[0] > 0.f ? acc[0] : 0.01f * acc[0];
        r.y = acc[1] > 0.f ? acc[1] : 0.01f * acc[1];
        r.z = acc[2] > 0.f ? acc[2] : 0.01f * acc[2];
        r.w = acc[3] > 0.f ? acc[3] : 0.01f * acc[3];
        *(float4*)&out[((size_t)n * 2048 + t0 + tl) * 64 + o0] = r;
    }
}

// ---------------- launch ----------------
extern "C" void kernel_launch(void* const* d_in, const int* in_sizes, int n_in,
                              void* d_out, int out_size) {
    (void)in_sizes; (void)n_in; (void)out_size;
    const float* poses = (const float*)d_in[0];
    const float* A1 = (const float*)d_in[1];
    const float* A2 = (const float*)d_in[2];
    const float* w1 = (const float*)d_in[3];
    const float* b1 = (const float*)d_in[4];
    const float* g1 = (const float*)d_in[5];
    const float* be1 = (const float*)d_in[6];
    const float* m1 = (const float*)d_in[7];
    const float* v1 = (const float*)d_in[8];
    const float* w2 = (const float*)d_in[9];
    const float* b2 = (const float*)d_in[10];
    const float* g2 = (const float*)d_in[11];
    const float* be2 = (const float*)d_in[12];
    const float* m2 = (const float*)d_in[13];
    const float* v2 = (const float*)d_in[14];
    const float* w3 = (const float*)d_in[15];
    const float* b3 = (const float*)d_in[16];
    const float* g3 = (const float*)d_in[17];
    const float* be3 = (const float*)d_in[18];
    const float* m3 = (const float*)d_in[19];
    const float* v3 = (const float*)d_in[20];
    const float* w4 = (const float*)d_in[21];
    const float* b4 = (const float*)d_in[22];
    const float* g4 = (const float*)d_in[23];
    const float* be4 = (const float*)d_in[24];
    const float* m4 = (const float*)d_in[25];
    const float* v4 = (const float*)d_in[26];
    float* out = (float*)d_out;

    size_t sm1 = 83712;
    size_t sm2 = 59904;
    size_t sm34 = (96 * 144 + 16 * 132 + 16 * 481) * sizeof(float);  // 94528
    cudaFuncSetAttribute(k1, cudaFuncAttributeMaxDynamicSharedMemorySize, (int)sm1);
    cudaFuncSetAttribute(k2, cudaFuncAttributeMaxDynamicSharedMemorySize, (int)sm2);
    cudaFuncSetAttribute(k34, cudaFuncAttributeMaxDynamicSharedMemorySize, (int)sm34);

    prepAll<<<656, 256>>>(poses,
                          A1, w1, b1, g1, be1, m1, v1,
                          A2, w2, b2, g2, be2, m2, v2,
                          w3, b3, g3, be3, m3, v3,
                          w4, b4, g4, be4, m4, v4);
    k1<<<dim3(8, 16, 4), 256, sm1>>>();
    k2<<<dim3(8, 16, 2), 256, sm2>>>();
    k34<<<dim3(16, 16), 256, sm34>>>(out);
}

// round 12
// speedup vs baseline: 1.2640x; 1.0252x over previous
#include <cuda_runtime.h>
#include <cuda_fp16.h>

#define EPSV 1e-5f

// ---------------- device scratch ----------------
__device__ __align__(16) unsigned short g_W1h[36 * 17 * 16 * 24];   // fp16
__device__ __align__(16) unsigned short g_W2h[153 * 6 * 16 * 24];   // fp16
__device__ __align__(16) unsigned short g_W3t[30 * 16 * 24];        // fp16 f3 tiles [ck=cc*5+dt]
__device__ float g_B1[272];
__device__ float g_B2[96];
__device__ float g_B3[16];
__device__ float g_W4t[48 * 64];     // [k=c*3+dk][o]
__device__ float g_B4[64];
__device__ __align__(16) unsigned short g_Ph[16 * 2048 * 64];
__device__ __align__(16) unsigned short g_Pl[16 * 2048 * 64];
__device__ __align__(16) unsigned short g_f1h[16 * 272 * 2048];
__device__ __align__(16) unsigned short g_f1l[16 * 272 * 2048];
__device__ float g_f2[16 * 96 * 2048];    // K-split partial 0 (with bias)
__device__ float g_f2b[16 * 96 * 2048];   // K-split partial 1

__constant__ int c_part_of[17] = {1,2,3,1,1,4,4,5,5,2,2,3,3,0,0,0,0};
__constant__ int c_idx_of[17]  = {0,0,0,1,2,0,1,0,1,1,2,1,2,0,1,2,3};
__constant__ int c_len_of[6]   = {4,3,3,3,2,2};

// ---------------- helpers ----------------
__device__ __forceinline__ void split_fp16(float x, unsigned short& h, unsigned short& l) {
    __half hh = __float2half_rn(x);
    float r = x - __half2float(hh);
    __half ll = __float2half_rn(r);
    h = __half_as_ushort(hh); l = __half_as_ushort(ll);
}
__device__ __forceinline__ void ldsm4(unsigned r[4], const void* p) {
    unsigned a = (unsigned)__cvta_generic_to_shared(p);
    asm volatile("ldmatrix.sync.aligned.m8n8.x4.shared.b16 {%0,%1,%2,%3},[%4];"
                 : "=r"(r[0]), "=r"(r[1]), "=r"(r[2]), "=r"(r[3]) : "r"(a));
}
__device__ __forceinline__ void mma_fp16(float* c, const unsigned* a, unsigned b0, unsigned b1) {
    asm volatile("mma.sync.aligned.m16n8k16.row.col.f32.f16.f16.f32 "
                 "{%0,%1,%2,%3},{%4,%5,%6,%7},{%8,%9},{%0,%1,%2,%3};"
                 : "+f"(c[0]), "+f"(c[1]), "+f"(c[2]), "+f"(c[3])
                 : "r"(a[0]), "r"(a[1]), "r"(a[2]), "r"(a[3]), "r"(b0), "r"(b1));
}
__device__ __forceinline__ void cpa16(void* dst, const void* src) {
    unsigned d = (unsigned)__cvta_generic_to_shared(dst);
    asm volatile("cp.async.cg.shared.global [%0], [%1], 16;" :: "r"(d), "l"(src));
}
__device__ __forceinline__ void cpa16z(void* dst, const void* src, bool valid) {
    unsigned d = (unsigned)__cvta_generic_to_shared(dst);
    int sz = valid ? 16 : 0;
    asm volatile("cp.async.cg.shared.global [%0], [%1], 16, %2;" :: "r"(d), "l"(src), "r"(sz));
}
#define CP_COMMIT() asm volatile("cp.async.commit_group;")
#define CP_WAIT0()  asm volatile("cp.async.wait_group 0;")

// ---------------- fused prep (638 blocks x 256 thr) ----------------
__global__ void prepAll(const float* __restrict__ poses,
                        const float* __restrict__ A1, const float* __restrict__ w1,
                        const float* __restrict__ b1, const float* __restrict__ g1,
                        const float* __restrict__ be1, const float* __restrict__ m1,
                        const float* __restrict__ v1,
                        const float* __restrict__ A2, const float* __restrict__ w2,
                        const float* __restrict__ b2, const float* __restrict__ g2,
                        const float* __restrict__ be2, const float* __restrict__ m2,
                        const float* __restrict__ v2,
                        const float* __restrict__ w3, const float* __restrict__ b3,
                        const float* __restrict__ g3, const float* __restrict__ be3,
                        const float* __restrict__ m3, const float* __restrict__ v3,
                        const float* __restrict__ w4, const float* __restrict__ b4,
                        const float* __restrict__ g4, const float* __restrict__ be4,
                        const float* __restrict__ m4, const float* __restrict__ v4) {
    const int bid = blockIdx.x;
    if (bid < 256) {
        const int n = bid >> 4, tb = (bid & 15) * 128;
        for (int idx = threadIdx.x; idx < 128 * 64; idx += 256) {
            int tl = idx >> 6, col = idx & 63;
            int t = tb + tl;
            float v = (col < 51) ? poses[((size_t)n * 2048 + t) * 51 + col] : 0.f;
            unsigned short h, l; split_fp16(v, h, l);
            size_t o = ((size_t)n * 2048 + t) * 64 + col;
            g_Ph[o] = h; g_Pl[o] = l;
        }
    } else if (bid < 528) {
        int cw = bid - 256;
        int c = cw / 17, w = cw % 17;
        int mt = cw >> 4, row = cw & 15;
        float s = g1[cw] * rsqrtf(v1[cw] + EPSV);
        for (int e = threadIdx.x; e < 36 * 24; e += 256) {
            int it = e / 24, col = e % 24;
            int dt = it >> 2, rc = it & 3;
            int r = rc * 16 + col;
            float val = 0.f;
            if (col < 16 && r < 51) {
                int u = r / 3, ci = r % 3;
                for (int k = 0; k < 5; k++)
                    for (int dv = 0; dv < 5; dv++) {
                        int v = u - dv + 2;
                        if (v >= 0 && v < 17)
                            val += A1[(k * 17 + v) * 17 + w] *
                                   w1[(((k * 16 + c) * 3 + ci) * 9 + dt) * 5 + dv];
                    }
                val *= s;
            }
            g_W1h[((it * 17 + mt) * 16 + row) * 24 + col] =
                __half_as_ushort(__float2half_rn(val));
        }
        if (threadIdx.x == 0) {
            float bias = 0.f;
            for (int k = 0; k < 5; k++) {
                float sa = 0.f;
                for (int v = 0; v < 17; v++) sa += A1[(k * 17 + v) * 17 + w];
                bias += b1[k * 16 + c] * sa;
            }
            g_B1[cw] = (bias - m1[cw]) * s + be1[cw];
        }
    } else if (bid < 624) {
        int cw = bid - 528;
        int c = cw / 6, w = cw % 6;
        int mt = cw >> 4, row = cw & 15;
        float s = g2[cw] * rsqrtf(v2[cw] + EPSV);
        for (int e = threadIdx.x; e < 153 * 24; e += 256) {
            int it = e / 24, col = e % 24;
            int cc = it / 9, dt = it % 9;
            int ch = cc * 16 + col;
            float val = 0.f;
            if (col < 16) {
                int f = ch / 17, jt = ch % 17;
                int p = c_part_of[jt], j = c_idx_of[jt], ln = c_len_of[p];
                int ci = f * ln + j;
                for (int k = 0; k < 5; k++)
                    for (int v = 0; v < 6; v++) {
                        int dp = p - v + 1;
                        if (dp >= 0 && dp < 3)
                            val += A2[(k * 6 + v) * 6 + w] *
                                   w2[(((k * 16 + c) * 64 + ci) * 9 + dt) * 3 + dp];
                    }
                val *= s;
            }
            g_W2h[((it * 6 + mt) * 16 + row) * 24 + col] =
                __half_as_ushort(__float2half_rn(val));
        }
        if (threadIdx.x == 0) {
            float bias = 0.f;
            for (int k = 0; k < 5; k++) {
                float sa = 0.f;
                for (int v = 0; v < 6; v++) sa += A2[(k * 6 + v) * 6 + w];
                bias += b2[k * 16 + c] * sa;
            }
            g_B2[cw] = (bias - m2[cw]) * s + be2[cw];
        }
    } else if (bid < 636) {
        int base = (bid - 624) * 256 + threadIdx.x;     // [0, 3072)
        if (base < 3072) {
            int o = base / 48, k = base % 48;
            g_W4t[k * 64 + o] = w4[base] * (g4[o] * rsqrtf(v4[o] + EPSV));
        }
        if (base < 16) {
            float s = g3[base] * rsqrtf(v3[base] + EPSV);
            g_B3[base] = (b3[base] - m3[base]) * s + be3[base];
        }
        if (base >= 32 && base < 96) {
            int o = base - 32;
            float s = g4[o] * rsqrtf(v4[o] + EPSV);
            g_B4[o] = (b4[o] - m4[o]) * s + be4[o];
        }
    } else {
        // W3 fp16 tiles: 30 chunks (ck=cc*5+dt) x [16 o rows][24 cols]
        int half = bid - 636;  // 0,1
        for (int e = half * 5760 + threadIdx.x; e < half * 5760 + 5760; e += 256) {
            int ck = e / 384, rem = e - ck * 384;
            int o = rem / 24, col = rem % 24;
            int cc = ck / 5, dt = ck % 5;
            float val = 0.f;
            if (col < 16) {
                float s = g3[o] * rsqrtf(v3[o] + EPSV);
                val = w3[o * 480 + (cc * 16 + col) * 5 + dt] * s;
            }
            g_W3t[(ck * 16 + o) * 24 + col] = __half_as_ushort(__float2half_rn(val));
        }
    }
}

// ---------------- stage 1 tensor GEMM (fp16 2-term) ----------------
#define K1_XOFF 7680
#define K1_XSZ  38016
__global__ void __launch_bounds__(256, 2) k1() {
    extern __shared__ char sm[];
    const int n = blockIdx.y, t0 = blockIdx.x * 256;
    const int z = blockIdx.z;
    const int mt0 = (z == 0) ? 0 : 1 + z * 4;
    const int mcount = (z == 0) ? 5 : 4;
    const int tid = threadIdx.x, lane = tid & 31, w = tid >> 5;
    char* Xh = sm + K1_XOFF;
    char* Xl = sm + K1_XOFF + K1_XSZ;

    auto prefW = [&](int it, char* buf) {
        const char* srcH = (const char*)(g_W1h + (size_t)(it * 17 + mt0) * 384);
        int cnt = mcount * 48;
        for (int i = tid; i < cnt; i += 256) cpa16(buf + i * 16, srcH + i * 16);
    };
    for (int i = tid; i < 264 * 8; i += 256) {
        int row = i >> 3, q = i & 7;
        int t = t0 - 4 + row;
        bool valid = (t >= 0 && t < 2048);
        size_t so = ((size_t)n * 2048 + (valid ? t : 0)) * 64 + q * 8;
        cpa16z(Xh + row * 144 + q * 16, g_Ph + so, valid);
        cpa16z(Xl + row * 144 + q * 16, g_Pl + so, valid);
    }
    prefW(0, sm); CP_COMMIT();

    float C[5][4][4];
#pragma unroll
    for (int i = 0; i < 5; i++)
#pragma unroll
        for (int j = 0; j < 4; j++)
#pragma unroll
            for (int q = 0; q < 4; q++) C[i][j][q] = 0.f;
    const int lrow = (lane & 15) * 48 + (lane >> 4) * 16;

    for (int it = 0; it < 36; it++) {
        char* buf = sm + (it & 1) * 3840;
        CP_WAIT0();
        __syncthreads();
        if (it + 1 < 36) { prefW(it + 1, sm + ((it + 1) & 1) * 3840); CP_COMMIT(); }
        const int dt = it >> 2, rc = it & 3;
        const int colb = (rc * 16 + (lane & 3) * 2) * 2;
        unsigned bh[4][2], bl[4][2];
#pragma unroll
        for (int nb = 0; nb < 4; nb++) {
            int tt = w * 32 + nb * 8 + (lane >> 2) + dt;
            const char* ph = Xh + tt * 144 + colb;
            const char* pl = Xl + tt * 144 + colb;
            bh[nb][0] = *(const unsigned*)ph; bh[nb][1] = *(const unsigned*)(ph + 16);
            bl[nb][0] = *(const unsigned*)pl; bl[nb][1] = *(const unsigned*)(pl + 16);
        }
        for (int mi = 0; mi < mcount; mi++) {
            unsigned Ah[4];
            ldsm4(Ah, buf + mi * 768 + lrow);
#pragma unroll
            for (int nb = 0; nb < 4; nb++) {
                mma_fp16(C[mi][nb], Ah, bh[nb][0], bh[nb][1]);
                mma_fp16(C[mi][nb], Ah, bl[nb][0], bl[nb][1]);
            }
        }
    }
    for (int mi = 0; mi < mcount; mi++) {
#pragma unroll
        for (int nb = 0; nb < 4; nb++) {
            int ch0 = (mt0 + mi) * 16 + (lane >> 2);
            int tt = t0 + w * 32 + nb * 8 + (lane & 3) * 2;
            float b0 = g_B1[ch0], b1 = g_B1[ch0 + 8];
            unsigned short h0, l0, h1, l1;
            size_t o0 = ((size_t)n * 272 + ch0) * 2048 + tt;
            split_fp16(C[mi][nb][0] + b0, h0, l0);
            split_fp16(C[mi][nb][1] + b0, h1, l1);
            *(unsigned*)&g_f1h[o0] = (unsigned)h0 | ((unsigned)h1 << 16);
            *(unsigned*)&g_f1l[o0] = (unsigned)l0 | ((unsigned)l1 << 16);
            size_t o1 = ((size_t)n * 272 + ch0 + 8) * 2048 + tt;
            split_fp16(C[mi][nb][2] + b1, h0, l0);
            split_fp16(C[mi][nb][3] + b1, h1, l1);
            *(unsigned*)&g_f1h[o1] = (unsigned)h0 | ((unsigned)h1 << 16);
            *(unsigned*)&g_f1l[o1] = (unsigned)l0 | ((unsigned)l1 << 16);
        }
    }
}

// ---------------- stage 2 tensor GEMM (fp16 2-term, K-split over z) ----------------
#define K2_WSZ 9216
#define K2_XB  25344
__global__ void __launch_bounds__(256, 2) k2() {
    extern __shared__ char sm[];
    const int n = blockIdx.y, t0 = blockIdx.x * 256;
    const int zz = blockIdx.z;
    const int cc0 = zz ? 9 : 0;
    const int ncc = zz ? 8 : 9;
    const int tid = threadIdx.x, lane = tid & 31, w = tid >> 5;
    const int g = tid & 15, jj = tid >> 4;
    unsigned sh[9], sl[9];

    auto prefW = [&](int it, char* buf) {
        const char* srcH = (const char*)(g_W2h + (size_t)it * 2304);
        for (int i = tid; i < 288; i += 256) cpa16(buf + i * 16, srcH + i * 16);
    };
    auto loadX = [&](int cc) {
        size_t base = ((size_t)n * 272 + cc * 16 + g) * 2048;
#pragma unroll
        for (int i = 0; i < 9; i++) {
            int p = jj + 16 * i;
            sh[i] = 0; sl[i] = 0;
            if (p < 132) {
                int t = t0 - 4 + 2 * p;
                if (t >= 0 && t < 2048) {
                    sh[i] = *(const unsigned*)(g_f1h + base + t);
                    sl[i] = *(const unsigned*)(g_f1l + base + t);
                }
            }
        }
    };
    auto stsX = [&](int buf) {
        unsigned short* Xh = (unsigned short*)(sm + K2_WSZ + buf * K2_XB);
        unsigned short* Xl = (unsigned short*)(sm + K2_WSZ + buf * K2_XB + 12672);
#pragma unroll
        for (int i = 0; i < 9; i++) {
            int p = jj + 16 * i;
            if (p < 132) {
                Xh[(2 * p) * 24 + g] = (unsigned short)(sh[i] & 0xffff);
                Xh[(2 * p + 1) * 24 + g] = (unsigned short)(sh[i] >> 16);
                Xl[(2 * p) * 24 + g] = (unsigned short)(sl[i] & 0xffff);
                Xl[(2 * p + 1) * 24 + g] = (unsigned short)(sl[i] >> 16);
            }
        }
    };

    loadX(cc0);
    stsX(0);
    prefW(cc0 * 9, sm);
    CP_COMMIT();

    float C[6][4][4];
#pragma unroll
    for (int i = 0; i < 6; i++)
#pragma unroll
        for (int j = 0; j < 4; j++)
#pragma unroll
            for (int q = 0; q < 4; q++) C[i][j][q] = 0.f;

    const int lrow = (lane & 15) * 48 + (lane >> 4) * 16;
    const int colb = ((lane & 3) * 2) * 2;
    const int nit = ncc * 9;

    for (int i = 0; i < nit; i++) {
        const int ccl = i / 9, dt = i - ccl * 9;
        char* buf = sm + (i & 1) * 4608;
        CP_WAIT0();
        __syncthreads();
        if (i + 1 < nit) { prefW(cc0 * 9 + i + 1, sm + ((i + 1) & 1) * 4608); CP_COMMIT(); }
        if (dt == 0 && ccl + 1 < ncc) loadX(cc0 + ccl + 1);
        if (dt == 7 && ccl + 1 < ncc) stsX((ccl + 1) & 1);

        const char* Xh = sm + K2_WSZ + (ccl & 1) * K2_XB;
        const char* Xl = Xh + 12672;
        unsigned bh[4][2], bl[4][2];
#pragma unroll
        for (int nb = 0; nb < 4; nb++) {
            int tt = w * 32 + nb * 8 + (lane >> 2) + dt;
            const char* ph = Xh + tt * 48 + colb;
            const char* pl = Xl + tt * 48 + colb;
            bh[nb][0] = *(const unsigned*)ph; bh[nb][1] = *(const unsigned*)(ph + 16);
            bl[nb][0] = *(const unsigned*)pl; bl[nb][1] = *(const unsigned*)(pl + 16);
        }
#pragma unroll
        for (int mi = 0; mi < 6; mi++) {
            unsigned Ah[4];
            ldsm4(Ah, buf + mi * 768 + lrow);
#pragma unroll
            for (int nb = 0; nb < 4; nb++) {
                mma_fp16(C[mi][nb], Ah, bh[nb][0], bh[nb][1]);
                mma_fp16(C[mi][nb], Ah, bl[nb][0], bl[nb][1]);
            }
        }
    }

    float* dst = zz ? g_f2b : g_f2;
#pragma unroll
    for (int mi = 0; mi < 6; mi++) {
#pragma unroll
        for (int nb = 0; nb < 4; nb++) {
            int ch0 = mi * 16 + (lane >> 2);
            int tt = t0 + w * 32 + nb * 8 + (lane & 3) * 2;
            float b0 = zz ? 0.f : g_B2[ch0];
            float b1 = zz ? 0.f : g_B2[ch0 + 8];
            float2 v0 = make_float2(C[mi][nb][0] + b0, C[mi][nb][1] + b0);
            float2 v1 = make_float2(C[mi][nb][2] + b1, C[mi][nb][3] + b1);
            *(float2*)&dst[((size_t)n * 96 + ch0) * 2048 + tt] = v0;
            *(float2*)&dst[((size_t)n * 96 + ch0 + 8) * 2048 + tt] = v1;
        }
    }
}

// ---------------- stages 3+4: f3 via tensor cores, f4 scalar ----------------
// smem: Xh [144 rows][104 ushort] 29952 | Xl 29952 | Wt 23040 | F3s 16x132 f32 8448 = 91392
__global__ void __launch_bounds__(256, 2) k34(float* __restrict__ out) {
    extern __shared__ char smc[];
    unsigned short* Xh = (unsigned short*)smc;
    unsigned short* Xl = (unsigned short*)(smc + 29952);
    char* Wt = smc + 59904;
    float* F3s = (float*)(smc + 82944);
    const int n = blockIdx.y;
    const int t0 = blockIdx.x * 128;
    const int tid = threadIdx.x, lane = tid & 31, w = tid >> 5;

    // preload all 30 W3 tiles (23040 B)
    for (int i = tid; i < 1440; i += 256) cpa16(Wt + i * 16, (const char*)g_W3t + i * 16);
    CP_COMMIT();

    // build X: row xr holds f2[.][t0-4+xr], summed partials, split fp16
    for (int idx = tid; idx < 96 * 144; idx += 256) {
        int ch = idx / 144, xr = idx - ch * 144;
        int t = t0 - 4 + xr;
        float v = 0.f;
        if (t >= 0 && t < 2048) {
            size_t o = ((size_t)n * 96 + ch) * 2048 + t;
            v = g_f2[o] + g_f2b[o];
        }
        unsigned short h, l; split_fp16(v, h, l);
        Xh[xr * 104 + ch] = h; Xl[xr * 104 + ch] = l;
    }
    CP_WAIT0();
    __syncthreads();

    // f3 GEMM: M=16, K=30x16, N=136 (s = t-t0+1 in [0,136))
    float C[3][4];
#pragma unroll
    for (int q = 0; q < 3; q++)
#pragma unroll
        for (int j = 0; j < 4; j++) C[q][j] = 0.f;
    const int nnb = (w == 0) ? 3 : 2;
    int nbs[3]; nbs[0] = w; nbs[1] = 8 + w; nbs[2] = 16;
    const int lrow = (lane & 15) * 48 + (lane >> 4) * 16;

    for (int ck = 0; ck < 30; ck++) {
        const int cc = ck / 5, dt = ck % 5;
        unsigned A[4];
        ldsm4(A, Wt + ck * 768 + lrow);
#pragma unroll
        for (int q = 0; q < 3; q++) {
            if (q >= nnb) break;
            int srow = nbs[q] * 8 + (lane >> 2);
            int xr = srow + dt + 1;
            const char* ph = (const char*)Xh + xr * 208 + cc * 32 + (lane & 3) * 4;
            const char* pl = (const char*)Xl + xr * 208 + cc * 32 + (lane & 3) * 4;
            unsigned bh0 = *(const unsigned*)ph, bh1 = *(const unsigned*)(ph + 16);
            unsigned bl0 = *(const unsigned*)pl, bl1 = *(const unsigned*)(pl + 16);
            mma_fp16(C[q], A, bh0, bh1);
            mma_fp16(C[q], A, bl0, bl1);
        }
    }
    // epilogue: bias + leaky -> F3s[o*132 + s], s = t-t0+1
    {
        int o0 = lane >> 2;
        float bb0 = __ldg(&g_B3[o0]), bb1 = __ldg(&g_B3[o0 + 8]);
#pragma unroll
        for (int q = 0; q < 3; q++) {
            if (q >= nnb) break;
            int s0 = nbs[q] * 8 + (lane & 3) * 2;
#pragma unroll
            for (int j = 0; j < 2; j++) {
                int s = s0 + j;
                if (s < 132) {
                    int t3 = t0 - 1 + s;
                    float a = C[q][j] + bb0;
                    float b = C[q][2 + j] + bb1;
                    float va = (t3 >= 0 && t3 < 2048) ? (a > 0.f ? a : 0.01f * a) : 0.f;
                    float vb = (t3 >= 0 && t3 < 2048) ? (b > 0.f ? b : 0.01f * b) : 0.f;
                    F3s[o0 * 132 + s] = va;
                    F3s[(o0 + 8) * 132 + s] = vb;
                }
            }
        }
    }
    __syncthreads();

    // f4 scalar (reads F3s[c*132 + tl + dk], tl+dk <= 129)
#pragma unroll
    for (int u = 0; u < 8; u++) {
        int idx = tid + u * 256;
        int tl = idx & 127, o0 = (idx >> 7) * 4;
        float acc[4];
#pragma unroll
        for (int i = 0; i < 4; i++) acc[i] = __ldg(&g_B4[o0 + i]);
        for (int c = 0; c < 16; c++) {
            float fv[3] = {F3s[c * 132 + tl], F3s[c * 132 + tl + 1], F3s[c * 132 + tl + 2]};
#pragma unroll
            for (int dk = 0; dk < 3; dk++) {
                float4 wv = __ldg((const float4*)(g_W4t + (c * 3 + dk) * 64 + o0));
                acc[0] = fmaf(wv.x, fv[dk], acc[0]);
                acc[1] = fmaf(wv.y, fv[dk], acc[1]);
                acc[2] = fmaf(wv.z, fv[dk], acc[2]);
                acc[3] = fmaf(wv.w, fv[dk], acc[3]);
            }
        }
        float4 r;
        r.x = acc[0] > 0.f ? acc[0] : 0.01f * acc[0];
        r.y = acc[1] > 0.f ? acc[1] : 0.01f * acc[1];
        r.z = acc[2] > 0.f ? acc[2] : 0.01f * acc[2];
        r.w = acc[3] > 0.f ? acc[3] : 0.01f * acc[3];
        *(float4*)&out[((size_t)n * 2048 + t0 + tl) * 64 + o0] = r;
    }
}

// ---------------- launch ----------------
extern "C" void kernel_launch(void* const* d_in, const int* in_sizes, int n_in,
                              void* d_out, int out_size) {
    (void)in_sizes; (void)n_in; (void)out_size;
    const float* poses = (const float*)d_in[0];
    const float* A1 = (const float*)d_in[1];
    const float* A2 = (const float*)d_in[2];
    const float* w1 = (const float*)d_in[3];
    const float* b1 = (const float*)d_in[4];
    const float* g1 = (const float*)d_in[5];
    const float* be1 = (const float*)d_in[6];
    const float* m1 = (const float*)d_in[7];
    const float* v1 = (const float*)d_in[8];
    const float* w2 = (const float*)d_in[9];
    const float* b2 = (const float*)d_in[10];
    const float* g2 = (const float*)d_in[11];
    const float* be2 = (const float*)d_in[12];
    const float* m2 = (const float*)d_in[13];
    const float* v2 = (const float*)d_in[14];
    const float* w3 = (const float*)d_in[15];
    const float* b3 = (const float*)d_in[16];
    const float* g3 = (const float*)d_in[17];
    const float* be3 = (const float*)d_in[18];
    const float* m3 = (const float*)d_in[19];
    const float* v3 = (const float*)d_in[20];
    const float* w4 = (const float*)d_in[21];
    const float* b4 = (const float*)d_in[22];
    const float* g4 = (const float*)d_in[23];
    const float* be4 = (const float*)d_in[24];
    const float* m4 = (const float*)d_in[25];
    const float* v4 = (const float*)d_in[26];
    float* out = (float*)d_out;

    size_t sm1 = 83712;
    size_t sm2 = 59904;
    size_t sm34 = 91392;
    cudaFuncSetAttribute(k1, cudaFuncAttributeMaxDynamicSharedMemorySize, (int)sm1);
    cudaFuncSetAttribute(k2, cudaFuncAttributeMaxDynamicSharedMemorySize, (int)sm2);
    cudaFuncSetAttribute(k34, cudaFuncAttributeMaxDynamicSharedMemorySize, (int)sm34);

    prepAll<<<638, 256>>>(poses,
                          A1, w1, b1, g1, be1, m1, v1,
                          A2, w2, b2, g2, be2, m2, v2,
                          w3, b3, g3, be3, m3, v3,
                          w4, b4, g4, be4, m4, v4);
    k1<<<dim3(8, 16, 4), 256, sm1>>>();
    k2<<<dim3(8, 16, 2), 256, sm2>>>();
    k34<<<dim3(16, 16), 256, sm34>>>(out);
}